// round 13
// baseline (speedup 1.0000x reference)
#include <cuda_runtime.h>
#include <math.h>

#define NLEV   16
#define NDENSE 12
#define NCONS  4
#define TSIZE  524288
#define HPRIME 2654435761u
#define HMASK  524287u
#define BLK    256

// Dense-level resolutions (float32 np.power chain margins all >> ulp error).
__device__ __constant__ int   RESD[NDENSE] = {16,22,30,42,58,80,111,153,212,294,406,561};
__device__ __constant__ float GSD[NDENSE] = {
    (float)(2048.0/16.0),  (float)(2048.0/22.0),  (float)(2048.0/30.0),
    (float)(2048.0/42.0),  (float)(2048.0/58.0),  (float)(2048.0/80.0),
    (float)(2048.0/111.0), (float)(2048.0/153.0), (float)(2048.0/212.0),
    (float)(2048.0/294.0), (float)(2048.0/406.0), (float)(2048.0/561.0)
};

// Quad table: g_quad[(QOFF[l]+c)*8 ..] = table_l[c], table_l[c+1],
// table_l[c+res], table_l[c+res+1] (8 floats = 32B per cell).
// One 32B v8 load fetches ALL FOUR corners of a dense cell.
#define QTOTAL 661844
__device__ __align__(32) float g_quad[QTOTAL * 8];
__constant__ int QOFF[13] = {0,274,782,1714,3522,6946,13428,25862,49426,
                             94584,181316,346560,661844};

// Build the quad table (runs inside the captured graph; coalesced, ~10us).
__global__ void fill_quad_kernel(const float* __restrict__ tables)
{
    int idx = blockIdx.x * BLK + threadIdx.x;
    if (idx >= QTOTAL) return;
    int l = 0;
#pragma unroll
    for (int i = 1; i < NDENSE; i++) if (idx >= QOFF[i]) l = i;
    int c   = idx - QOFF[l];
    int res = RESD[l];
    const float2* tb2 = (const float2*)tables + (size_t)l * TSIZE;
    float2 e0 = __ldg(tb2 + c);
    float2 e1 = __ldg(tb2 + c + 1);
    float2 e2 = __ldg(tb2 + c + res);
    float2 e3 = __ldg(tb2 + c + res + 1);
    float* q = g_quad + (size_t)idx * 8;
    *(float4*)q       = make_float4(e0.x, e0.y, e1.x, e1.y);
    *(float4*)(q + 4) = make_float4(e2.x, e2.y, e3.x, e3.y);
}

// XLA:GPU emits approximate full-range division (div.full.f32) for f32 divide.
// Required for bit-exact bl = floor(x/gs) at cell boundaries.
__device__ __forceinline__ float div_full(float a, float b)
{
    float r;
    asm("div.full.f32 %0, %1, %2;" : "=f"(r) : "f"(a), "f"(b));
    return r;
}

// Exact replica of jnp.searchsorted(tk_row, 2h) -> where(k==n,0,k) -> tv[k].
__device__ __forceinline__ int cons_lookup(const int* __restrict__ tk,
                                           const int* __restrict__ tv,
                                           long long rowoff, int n, unsigned h)
{
    int q  = 2 * (int)h;
    int lo = 0, hi = n;
    while (lo < hi) {
        int mid = (lo + hi) >> 1;
        if (__ldg(tk + rowoff + mid) < q) lo = mid + 1; else hi = mid;
    }
    if (lo == n) lo = 0;
    return __ldg(tv + rowoff + lo);
}

// 4 threads per point; lane role g = t&3 owns levels {4g..4g+3}.
// g<3 lanes: all-dense — ONE 32B v8 load per level fetches all 4 corners.
// g=3 lane: all 4 hash levels. PARITY PAIRING: h10 = h00^1 whenever b0 is even
// (g0^(g0+1)=1 under the mask), same for h01/h11 — so an aligned LDG.128 at
// tb4[i>>1] covers a corner AND its XOR-1 buddy. Check is done on the actual
// indices (works through the searchsorted fallback too); the unpaired corner
// falls back to a predicated LDG.64. Avg hash loads/level: 4 -> ~3.
__global__ __launch_bounds__(BLK, 6)
void hashgrid_kernel(const float* __restrict__ x,
                     const float* __restrict__ tables,
                     const int*   __restrict__ tk,
                     const int*   __restrict__ tv,
                     const int*   __restrict__ lengths,
                     int L, int maxP,
                     float* __restrict__ out,
                     int npts)
{
    const int t = blockIdx.x * BLK + threadIdx.x;
    const int p = t >> 2;
    const int g = t & 3;
    const bool valid = (p < npts);
    const int  pl = valid ? p : (npts - 1);

    const float2 xv = __ldg((const float2*)x + pl);
    const float x0 = xv.x, x1 = xv.y;
    const size_t idxbase = (size_t)npts * 32;
    const int lvl0 = 4 * g;

    float w0s[4], w1s[4];
    float f[8];

    if (g < 3) {
        int cells[4];
        // ---- phase 1: cells + weights; idx outputs stored immediately ----
#pragma unroll
        for (int j = 0; j < 4; j++) {
            const int lvl = lvl0 + j;
            const int   res = RESD[lvl];
            const float gs  = GSD[lvl];

            float q0  = div_full(x0, gs);
            float q1  = div_full(x1, gs);
            float b0f = floorf(q0), b1f = floorf(q1);
            int   b0  = (int)b0f,   b1  = (int)b1f;
            float mn0 = b0f * gs,   mn1 = b1f * gs;
            w0s[j] = __fdividef(x0 - mn0, (mn0 + gs) - mn0);
            w1s[j] = __fdividef(x1 - mn1, (mn1 + gs) - mn1);

            int i00 = b0 * res + b1;
            cells[j] = i00;

            if (valid) {
                float4 v = make_float4((float)i00, (float)(i00 + 1),
                                       (float)(i00 + res), (float)(i00 + res + 1));
                __stcs((float4*)(out + idxbase + ((size_t)lvl * npts + p) * 4), v);
            }
        }

        // ---- phase 2: ONE v8 gather per level + interpolate ----
#pragma unroll
        for (int j = 0; j < 4; j++) {
            const int lvl = lvl0 + j;
            const float* qp = g_quad + (size_t)(QOFF[lvl] + cells[j]) * 8;
            float r0, r1, r2, r3, r4, r5, r6, r7;
            asm("ld.global.v8.f32 {%0,%1,%2,%3,%4,%5,%6,%7}, [%8];"
                : "=f"(r0), "=f"(r1), "=f"(r2), "=f"(r3),
                  "=f"(r4), "=f"(r5), "=f"(r6), "=f"(r7)
                : "l"(qp));

            float w0 = w0s[j], w1 = w1s[j];
            float om0 = 1.0f - w0, om1 = 1.0f - w1;
            float c0x = r0 * om1 + r2 * w1;
            float c0y = r1 * om1 + r3 * w1;
            float c1x = r4 * om1 + r6 * w1;
            float c1y = r5 * om1 + r7 * w1;
            f[2 * j]     = c0x * om0 + c1x * w0;
            f[2 * j + 1] = c0y * om0 + c1y * w0;
        }
    } else {
        int idxs[16];
        // ---- phase 1: hashes + weights; idx outputs stored immediately ----
#pragma unroll
        for (int j = 0; j < 4; j++) {
            const int lvl = lvl0 + j;
            int li  = (j < L) ? j : (L - 1);
            int len = __ldg(lengths + li);             // (res+1)^2, exact in f32
            int res = (int)__fsqrt_rn((float)len) - 1; // exact integer sqrt
            float gs = __fdiv_rn(2048.0f, (float)res); // == f64-then-f32 (proven)

            float q0  = div_full(x0, gs);
            float q1  = div_full(x1, gs);
            float b0f = floorf(q0), b1f = floorf(q1);
            int   b0  = (int)b0f,   b1  = (int)b1f;
            float mn0 = b0f * gs,   mn1 = b1f * gs;
            w0s[j] = __fdividef(x0 - mn0, (mn0 + gs) - mn0);
            w1s[j] = __fdividef(x1 - mn1, (mn1 + gs) - mn1);

            unsigned g0 = (unsigned)b0, g1 = (unsigned)b1;
            unsigned h00 = (g0        ^ (g1        * HPRIME)) & HMASK;
            unsigned h01 = (g0        ^ ((g1 + 1u) * HPRIME)) & HMASK;
            unsigned h10 = ((g0 + 1u) ^ (g1        * HPRIME)) & HMASK;
            unsigned h11 = ((g0 + 1u) ^ ((g1 + 1u) * HPRIME)) & HMASK;

            if ((unsigned)b0 < (unsigned)res && (unsigned)b1 < (unsigned)res) {
                // All 4 corners present in table => searchsorted returns the hash.
                idxs[4 * j + 0] = (int)h00; idxs[4 * j + 1] = (int)h01;
                idxs[4 * j + 2] = (int)h10; idxs[4 * j + 3] = (int)h11;
            } else {
                long long ro = (long long)li * maxP;
                idxs[4 * j + 0] = cons_lookup(tk, tv, ro, len, h00);
                idxs[4 * j + 1] = cons_lookup(tk, tv, ro, len, h01);
                idxs[4 * j + 2] = cons_lookup(tk, tv, ro, len, h10);
                idxs[4 * j + 3] = cons_lookup(tk, tv, ro, len, h11);
            }

            if (valid) {
                float4 v = make_float4((float)idxs[4 * j + 0], (float)idxs[4 * j + 1],
                                       (float)idxs[4 * j + 2], (float)idxs[4 * j + 3]);
                __stcs((float4*)(out + idxbase + ((size_t)lvl * npts + p) * 4), v);
            }
        }

        // ---- phase 2: pair-gathers + interpolate ----
#pragma unroll
        for (int j = 0; j < 4; j++) {
            const int lvl = lvl0 + j;
            const float2* tb  = (const float2*)tables + (size_t)lvl * TSIZE;
            const float4* tb4 = (const float4*)tb;

            int i00 = idxs[4 * j + 0], i01 = idxs[4 * j + 1];
            int i10 = idxs[4 * j + 2], i11 = idxs[4 * j + 3];

            // Each LDG.128 covers the corner and its XOR-1 buddy (in-bounds
            // always: buddy index < T).
            float4 v0 = __ldg(tb4 + (i00 >> 1));
            float4 v1 = __ldg(tb4 + (i01 >> 1));

            float2 e00 = (i00 & 1) ? make_float2(v0.z, v0.w) : make_float2(v0.x, v0.y);
            float2 bud0 = (i00 & 1) ? make_float2(v0.x, v0.y) : make_float2(v0.z, v0.w);
            float2 e01 = (i01 & 1) ? make_float2(v1.z, v1.w) : make_float2(v1.x, v1.y);
            float2 bud1 = (i01 & 1) ? make_float2(v1.x, v1.y) : make_float2(v1.z, v1.w);

            bool pair0 = (i10 == (i00 ^ 1));
            bool pair1 = (i11 == (i01 ^ 1));
            float2 e10 = bud0, e11 = bud1;
            if (!pair0) e10 = __ldg(tb + i10);   // predicated LDG.64
            if (!pair1) e11 = __ldg(tb + i11);

            float w0 = w0s[j], w1 = w1s[j];
            float om0 = 1.0f - w0, om1 = 1.0f - w1;
            float c0x = e00.x * om1 + e01.x * w1;
            float c1x = e10.x * om1 + e11.x * w1;
            float c0y = e00.y * om1 + e01.y * w1;
            float c1y = e10.y * om1 + e11.y * w1;
            f[2 * j]     = c0x * om0 + c1x * w0;
            f[2 * j + 1] = c0y * om0 + c1y * w0;
        }
    }

    // ---- phase 3: ONE 256-bit feat store ----
    if (valid) {
        float* dst = out + (size_t)p * 32 + 8 * g;     // 32B-aligned lane slice
        asm volatile(
            "st.global.cs.v8.f32 [%0], {%1,%2,%3,%4,%5,%6,%7,%8};"
            :: "l"(dst),
               "f"(f[0]), "f"(f[1]), "f"(f[2]), "f"(f[3]),
               "f"(f[4]), "f"(f[5]), "f"(f[6]), "f"(f[7])
            : "memory");
    }
}

extern "C" void kernel_launch(void* const* d_in, const int* in_sizes, int n_in,
                              void* d_out, int out_size)
{
    const float* x       = (const float*)d_in[0];
    const float* tables  = (const float*)d_in[1];
    const int*   tk      = (const int*)d_in[2];
    const int*   tv      = (const int*)d_in[3];
    const int*   lengths = (const int*)d_in[4];

    int L    = in_sizes[4];
    int maxP = in_sizes[2] / (L > 0 ? L : 1);
    int npts = in_sizes[0] / 2;

    fill_quad_kernel<<<(QTOTAL + BLK - 1) / BLK, BLK>>>(tables);

    long long nthreads = 4LL * npts;
    int blocks = (int)((nthreads + BLK - 1) / BLK);
    hashgrid_kernel<<<blocks, BLK>>>(x, tables, tk, tv, lengths, L, maxP,
                                     (float*)d_out, npts);
}

// round 14
// speedup vs baseline: 1.0816x; 1.0816x over previous
#include <cuda_runtime.h>
#include <math.h>

#define NLEV   16
#define NDENSE 12
#define NCONS  4
#define TSIZE  524288
#define HPRIME 2654435761u
#define HMASK  524287u
#define BLK    256
#define PTS_PER_BLK 64

// Dense-level resolutions (float32 np.power chain margins all >> ulp error).
__device__ __constant__ int   RESD[NDENSE] = {16,22,30,42,58,80,111,153,212,294,406,561};
__device__ __constant__ float GSD[NDENSE] = {
    (float)(2048.0/16.0),  (float)(2048.0/22.0),  (float)(2048.0/30.0),
    (float)(2048.0/42.0),  (float)(2048.0/58.0),  (float)(2048.0/80.0),
    (float)(2048.0/111.0), (float)(2048.0/153.0), (float)(2048.0/212.0),
    (float)(2048.0/294.0), (float)(2048.0/406.0), (float)(2048.0/561.0)
};

// Quad table: g_quad[(QOFF[l]+c)*8 ..] = table_l[c], table_l[c+1],
// table_l[c+res], table_l[c+res+1] (8 floats = 32B per cell).
// One 32B v8 load fetches ALL FOUR corners of a dense cell.
#define QTOTAL 661844
__device__ __align__(32) float g_quad[QTOTAL * 8];
__constant__ int QOFF[13] = {0,274,782,1714,3522,6946,13428,25862,49426,
                             94584,181316,346560,661844};

// Build the quad table (runs inside the captured graph; coalesced, few us).
__global__ void fill_quad_kernel(const float* __restrict__ tables)
{
    int idx = blockIdx.x * BLK + threadIdx.x;
    if (idx >= QTOTAL) return;
    int l = 0;
#pragma unroll
    for (int i = 1; i < NDENSE; i++) if (idx >= QOFF[i]) l = i;
    int c   = idx - QOFF[l];
    int res = RESD[l];
    const float2* tb2 = (const float2*)tables + (size_t)l * TSIZE;
    float2 e0 = __ldg(tb2 + c);
    float2 e1 = __ldg(tb2 + c + 1);
    float2 e2 = __ldg(tb2 + c + res);
    float2 e3 = __ldg(tb2 + c + res + 1);
    float* q = g_quad + (size_t)idx * 8;
    *(float4*)q       = make_float4(e0.x, e0.y, e1.x, e1.y);
    *(float4*)(q + 4) = make_float4(e2.x, e2.y, e3.x, e3.y);
}

// XLA:GPU emits approximate full-range division (div.full.f32) for f32 divide.
// Required for bit-exact bl = floor(x/gs) at cell boundaries.
__device__ __forceinline__ float div_full(float a, float b)
{
    float r;
    asm("div.full.f32 %0, %1, %2;" : "=f"(r) : "f"(a), "f"(b));
    return r;
}

// Exact replica of jnp.searchsorted(tk_row, 2h) -> where(k==n,0,k) -> tv[k].
__device__ __forceinline__ int cons_lookup(const int* __restrict__ tk,
                                           const int* __restrict__ tv,
                                           long long rowoff, int n, unsigned h)
{
    int q  = 2 * (int)h;
    int lo = 0, hi = n;
    while (lo < hi) {
        int mid = (lo + hi) >> 1;
        if (__ldg(tk + rowoff + mid) < q) lo = mid + 1; else hi = mid;
    }
    if (lo == n) lo = 0;
    return __ldg(tv + rowoff + lo);
}

// PER-WARP role split (kills the per-lane divergence of the g=t&3 scheme):
// block = 8 warps = 64 points.
//   warps 0-5 (192 thr): dense. d = wid*32+lane; pt = d/3; g = d%3 ->
//     levels {4g..4g+3}. Dense instructions now run at 100% lane efficiency
//     (was 75%).
//   warps 6-7 (64 thr): hash. pt = (wid-6)*32+lane; levels 12-15. Hash path
//     (incl. searchsorted fallback) at 100% lane efficiency (was 25%).
// Dense gathers: ONE 32B v8 quad load per level. CONS params inline from
// lengths (exact recovery, see comments). div.full for bl; __fdividef for w.
__global__ __launch_bounds__(BLK, 6)
void hashgrid_kernel(const float* __restrict__ x,
                     const float* __restrict__ tables,
                     const int*   __restrict__ tk,
                     const int*   __restrict__ tv,
                     const int*   __restrict__ lengths,
                     int L, int maxP,
                     float* __restrict__ out,
                     int npts)
{
    const int wid  = threadIdx.x >> 5;
    const int lane = threadIdx.x & 31;
    const int pbase = blockIdx.x * PTS_PER_BLK;
    const size_t idxbase = (size_t)npts * 32;

    float w0s[4], w1s[4];
    float f[8];

    if (wid < 6) {
        // ---------------- dense warps ----------------
        const int d  = wid * 32 + lane;
        const int pt = d / 3;                 // 0..63
        const int g  = d - 3 * pt;            // 0..2
        const int p  = pbase + pt;
        const bool valid = (p < npts);
        const int  pl = valid ? p : (npts - 1);
        const int lvl0 = 4 * g;

        const float2 xv = __ldg((const float2*)x + pl);
        const float x0 = xv.x, x1 = xv.y;

        int cells[4];
        // phase 1: cells + weights; idx outputs stored immediately
#pragma unroll
        for (int j = 0; j < 4; j++) {
            const int lvl = lvl0 + j;
            const int   res = RESD[lvl];
            const float gs  = GSD[lvl];

            float q0  = div_full(x0, gs);
            float q1  = div_full(x1, gs);
            float b0f = floorf(q0), b1f = floorf(q1);
            int   b0  = (int)b0f,   b1  = (int)b1f;
            float mn0 = b0f * gs,   mn1 = b1f * gs;
            w0s[j] = __fdividef(x0 - mn0, (mn0 + gs) - mn0);
            w1s[j] = __fdividef(x1 - mn1, (mn1 + gs) - mn1);

            int i00 = b0 * res + b1;
            cells[j] = i00;

            if (valid) {
                float4 v = make_float4((float)i00, (float)(i00 + 1),
                                       (float)(i00 + res), (float)(i00 + res + 1));
                __stcs((float4*)(out + idxbase + ((size_t)lvl * npts + p) * 4), v);
            }
        }

        // phase 2: ONE v8 gather per level + interpolate
#pragma unroll
        for (int j = 0; j < 4; j++) {
            const int lvl = lvl0 + j;
            const float* qp = g_quad + (size_t)(QOFF[lvl] + cells[j]) * 8;
            float r0, r1, r2, r3, r4, r5, r6, r7;
            asm("ld.global.v8.f32 {%0,%1,%2,%3,%4,%5,%6,%7}, [%8];"
                : "=f"(r0), "=f"(r1), "=f"(r2), "=f"(r3),
                  "=f"(r4), "=f"(r5), "=f"(r6), "=f"(r7)
                : "l"(qp));

            float w0 = w0s[j], w1 = w1s[j];
            float om0 = 1.0f - w0, om1 = 1.0f - w1;
            float c0x = r0 * om1 + r2 * w1;
            float c0y = r1 * om1 + r3 * w1;
            float c1x = r4 * om1 + r6 * w1;
            float c1y = r5 * om1 + r7 * w1;
            f[2 * j]     = c0x * om0 + c1x * w0;
            f[2 * j + 1] = c0y * om0 + c1y * w0;
        }

        // phase 3: ONE 256-bit feat store (32B-aligned lane slice)
        if (valid) {
            float* dst = out + (size_t)p * 32 + 8 * g;
            asm volatile(
                "st.global.cs.v8.f32 [%0], {%1,%2,%3,%4,%5,%6,%7,%8};"
                :: "l"(dst),
                   "f"(f[0]), "f"(f[1]), "f"(f[2]), "f"(f[3]),
                   "f"(f[4]), "f"(f[5]), "f"(f[6]), "f"(f[7])
                : "memory");
        }
    } else {
        // ---------------- hash warps (levels 12-15) ----------------
        const int p  = pbase + (wid - 6) * 32 + lane;
        const bool valid = (p < npts);
        const int  pl = valid ? p : (npts - 1);

        const float2 xv = __ldg((const float2*)x + pl);
        const float x0 = xv.x, x1 = xv.y;

        int idxs[16];
        // phase 1: hashes + weights; idx outputs stored immediately
#pragma unroll
        for (int j = 0; j < 4; j++) {
            const int lvl = NDENSE + j;
            int li  = (j < L) ? j : (L - 1);
            int len = __ldg(lengths + li);             // (res+1)^2, exact in f32
            int res = (int)__fsqrt_rn((float)len) - 1; // exact integer sqrt
            float gs = __fdiv_rn(2048.0f, (float)res); // == f64-then-f32 (proven)

            float q0  = div_full(x0, gs);
            float q1  = div_full(x1, gs);
            float b0f = floorf(q0), b1f = floorf(q1);
            int   b0  = (int)b0f,   b1  = (int)b1f;
            float mn0 = b0f * gs,   mn1 = b1f * gs;
            w0s[j] = __fdividef(x0 - mn0, (mn0 + gs) - mn0);
            w1s[j] = __fdividef(x1 - mn1, (mn1 + gs) - mn1);

            unsigned g0 = (unsigned)b0, g1 = (unsigned)b1;
            unsigned h00 = (g0        ^ (g1        * HPRIME)) & HMASK;
            unsigned h01 = (g0        ^ ((g1 + 1u) * HPRIME)) & HMASK;
            unsigned h10 = ((g0 + 1u) ^ (g1        * HPRIME)) & HMASK;
            unsigned h11 = ((g0 + 1u) ^ ((g1 + 1u) * HPRIME)) & HMASK;

            if ((unsigned)b0 < (unsigned)res && (unsigned)b1 < (unsigned)res) {
                // All 4 corners present in table => searchsorted returns the hash.
                idxs[4 * j + 0] = (int)h00; idxs[4 * j + 1] = (int)h01;
                idxs[4 * j + 2] = (int)h10; idxs[4 * j + 3] = (int)h11;
            } else {
                long long ro = (long long)li * maxP;
                idxs[4 * j + 0] = cons_lookup(tk, tv, ro, len, h00);
                idxs[4 * j + 1] = cons_lookup(tk, tv, ro, len, h01);
                idxs[4 * j + 2] = cons_lookup(tk, tv, ro, len, h10);
                idxs[4 * j + 3] = cons_lookup(tk, tv, ro, len, h11);
            }

            if (valid) {
                float4 v = make_float4((float)idxs[4 * j + 0], (float)idxs[4 * j + 1],
                                       (float)idxs[4 * j + 2], (float)idxs[4 * j + 3]);
                __stcs((float4*)(out + idxbase + ((size_t)lvl * npts + p) * 4), v);
            }
        }

        // phase 2: 4 independent random gathers per level + interpolate
#pragma unroll
        for (int j = 0; j < 4; j++) {
            const int lvl = NDENSE + j;
            const float2* tb = (const float2*)tables + (size_t)lvl * TSIZE;
            float2 e00 = __ldg(tb + idxs[4 * j + 0]);
            float2 e01 = __ldg(tb + idxs[4 * j + 1]);
            float2 e10 = __ldg(tb + idxs[4 * j + 2]);
            float2 e11 = __ldg(tb + idxs[4 * j + 3]);

            float w0 = w0s[j], w1 = w1s[j];
            float om0 = 1.0f - w0, om1 = 1.0f - w1;
            float c0x = e00.x * om1 + e01.x * w1;
            float c1x = e10.x * om1 + e11.x * w1;
            float c0y = e00.y * om1 + e01.y * w1;
            float c1y = e10.y * om1 + e11.y * w1;
            f[2 * j]     = c0x * om0 + c1x * w0;
            f[2 * j + 1] = c0y * om0 + c1y * w0;
        }

        // phase 3: ONE 256-bit feat store (point's levels 12-15 slice)
        if (valid) {
            float* dst = out + (size_t)p * 32 + 24;    // 32B-aligned
            asm volatile(
                "st.global.cs.v8.f32 [%0], {%1,%2,%3,%4,%5,%6,%7,%8};"
                :: "l"(dst),
                   "f"(f[0]), "f"(f[1]), "f"(f[2]), "f"(f[3]),
                   "f"(f[4]), "f"(f[5]), "f"(f[6]), "f"(f[7])
                : "memory");
        }
    }
}

extern "C" void kernel_launch(void* const* d_in, const int* in_sizes, int n_in,
                              void* d_out, int out_size)
{
    const float* x       = (const float*)d_in[0];
    const float* tables  = (const float*)d_in[1];
    const int*   tk      = (const int*)d_in[2];
    const int*   tv      = (const int*)d_in[3];
    const int*   lengths = (const int*)d_in[4];

    int L    = in_sizes[4];
    int maxP = in_sizes[2] / (L > 0 ? L : 1);
    int npts = in_sizes[0] / 2;

    fill_quad_kernel<<<(QTOTAL + BLK - 1) / BLK, BLK>>>(tables);

    int blocks = (npts + PTS_PER_BLK - 1) / PTS_PER_BLK;
    hashgrid_kernel<<<blocks, BLK>>>(x, tables, tk, tv, lengths, L, maxP,
                                     (float*)d_out, npts);
}

// round 15
// speedup vs baseline: 1.0960x; 1.0133x over previous
#include <cuda_runtime.h>
#include <math.h>

#define NLEV   16
#define NDENSE 12
#define NCONS  4
#define TSIZE  524288
#define HPRIME 2654435761u
#define HMASK  524287u
#define BLK    256          // fill kernel block
#define BLKT   160          // main kernel: 5 warps
#define PTS_PER_BLK 32

// Dense-level resolutions (float32 np.power chain margins all >> ulp error).
__device__ __constant__ int   RESD[NDENSE] = {16,22,30,42,58,80,111,153,212,294,406,561};
__device__ __constant__ float GSD[NDENSE] = {
    (float)(2048.0/16.0),  (float)(2048.0/22.0),  (float)(2048.0/30.0),
    (float)(2048.0/42.0),  (float)(2048.0/58.0),  (float)(2048.0/80.0),
    (float)(2048.0/111.0), (float)(2048.0/153.0), (float)(2048.0/212.0),
    (float)(2048.0/294.0), (float)(2048.0/406.0), (float)(2048.0/561.0)
};

// Quad table: g_quad[(QOFF[l]+c)*8 ..] = table_l[c], table_l[c+1],
// table_l[c+res], table_l[c+res+1] (8 floats = 32B per cell).
// One 32B v8 load fetches ALL FOUR corners of a dense cell.
#define QTOTAL 661844
__device__ __align__(32) float g_quad[QTOTAL * 8];
__constant__ int QOFF[13] = {0,274,782,1714,3522,6946,13428,25862,49426,
                             94584,181316,346560,661844};

// Build the quad table (runs inside the captured graph; coalesced, few us).
__global__ void fill_quad_kernel(const float* __restrict__ tables)
{
    int idx = blockIdx.x * BLK + threadIdx.x;
    if (idx >= QTOTAL) return;
    int l = 0;
#pragma unroll
    for (int i = 1; i < NDENSE; i++) if (idx >= QOFF[i]) l = i;
    int c   = idx - QOFF[l];
    int res = RESD[l];
    const float2* tb2 = (const float2*)tables + (size_t)l * TSIZE;
    float2 e0 = __ldg(tb2 + c);
    float2 e1 = __ldg(tb2 + c + 1);
    float2 e2 = __ldg(tb2 + c + res);
    float2 e3 = __ldg(tb2 + c + res + 1);
    float* q = g_quad + (size_t)idx * 8;
    *(float4*)q       = make_float4(e0.x, e0.y, e1.x, e1.y);
    *(float4*)(q + 4) = make_float4(e2.x, e2.y, e3.x, e3.y);
}

// XLA:GPU emits approximate full-range division (div.full.f32) for f32 divide.
// Required for bit-exact bl = floor(x/gs) at cell boundaries.
__device__ __forceinline__ float div_full(float a, float b)
{
    float r;
    asm("div.full.f32 %0, %1, %2;" : "=f"(r) : "f"(a), "f"(b));
    return r;
}

// Exact replica of jnp.searchsorted(tk_row, 2h) -> where(k==n,0,k) -> tv[k].
__device__ __forceinline__ int cons_lookup(const int* __restrict__ tk,
                                           const int* __restrict__ tv,
                                           long long rowoff, int n, unsigned h)
{
    int q  = 2 * (int)h;
    int lo = 0, hi = n;
    while (lo < hi) {
        int mid = (lo + hi) >> 1;
        if (__ldg(tk + rowoff + mid) < q) lo = mid + 1; else hi = mid;
    }
    if (lo == n) lo = 0;
    return __ldg(tv + rowoff + lo);
}

// BALANCED per-warp roles. Block = 5 warps = 32 points:
//   warps 0-2 (96 thr): dense. d = wid*32+lane; pt = d/3; g = d%3 ->
//     levels {4g..4g+3}; 4 v8 quad loads per thread.
//   warps 3-4 (64 thr): hash, 2 THREADS PER POINT. h = (wid-3)*32+lane;
//     pt = h>>1; half = h&1; levels {12+2*half, 13+2*half}; 8 random loads
//     per thread (was 16 -> matches dense per-thread memory work; removes
//     the straggler tail that capped occupancy at 56%).
// Dense gathers: ONE 32B v8 quad load per level. CONS params inline from
// lengths (exact recovery). div.full for bl; __fdividef for w.
__global__ __launch_bounds__(BLKT, 10)
void hashgrid_kernel(const float* __restrict__ x,
                     const float* __restrict__ tables,
                     const int*   __restrict__ tk,
                     const int*   __restrict__ tv,
                     const int*   __restrict__ lengths,
                     int L, int maxP,
                     float* __restrict__ out,
                     int npts)
{
    const int wid  = threadIdx.x >> 5;
    const int lane = threadIdx.x & 31;
    const int pbase = blockIdx.x * PTS_PER_BLK;
    const size_t idxbase = (size_t)npts * 32;

    if (wid < 3) {
        // ---------------- dense warps ----------------
        const int d  = wid * 32 + lane;       // 0..95
        const int pt = d / 3;                 // 0..31
        const int g  = d - 3 * pt;            // 0..2
        const int p  = pbase + pt;
        const bool valid = (p < npts);
        const int  pl = valid ? p : (npts - 1);
        const int lvl0 = 4 * g;

        const float2 xv = __ldg((const float2*)x + pl);
        const float x0 = xv.x, x1 = xv.y;

        float w0s[4], w1s[4], f[8];
        int cells[4];
#pragma unroll
        for (int j = 0; j < 4; j++) {
            const int lvl = lvl0 + j;
            const int   res = RESD[lvl];
            const float gs  = GSD[lvl];

            float q0  = div_full(x0, gs);
            float q1  = div_full(x1, gs);
            float b0f = floorf(q0), b1f = floorf(q1);
            int   b0  = (int)b0f,   b1  = (int)b1f;
            float mn0 = b0f * gs,   mn1 = b1f * gs;
            w0s[j] = __fdividef(x0 - mn0, (mn0 + gs) - mn0);
            w1s[j] = __fdividef(x1 - mn1, (mn1 + gs) - mn1);

            int i00 = b0 * res + b1;
            cells[j] = i00;

            if (valid) {
                float4 v = make_float4((float)i00, (float)(i00 + 1),
                                       (float)(i00 + res), (float)(i00 + res + 1));
                __stcs((float4*)(out + idxbase + ((size_t)lvl * npts + p) * 4), v);
            }
        }

#pragma unroll
        for (int j = 0; j < 4; j++) {
            const int lvl = lvl0 + j;
            const float* qp = g_quad + (size_t)(QOFF[lvl] + cells[j]) * 8;
            float r0, r1, r2, r3, r4, r5, r6, r7;
            asm("ld.global.v8.f32 {%0,%1,%2,%3,%4,%5,%6,%7}, [%8];"
                : "=f"(r0), "=f"(r1), "=f"(r2), "=f"(r3),
                  "=f"(r4), "=f"(r5), "=f"(r6), "=f"(r7)
                : "l"(qp));

            float w0 = w0s[j], w1 = w1s[j];
            float om0 = 1.0f - w0, om1 = 1.0f - w1;
            float c0x = r0 * om1 + r2 * w1;
            float c0y = r1 * om1 + r3 * w1;
            float c1x = r4 * om1 + r6 * w1;
            float c1y = r5 * om1 + r7 * w1;
            f[2 * j]     = c0x * om0 + c1x * w0;
            f[2 * j + 1] = c0y * om0 + c1y * w0;
        }

        if (valid) {
            float* dst = out + (size_t)p * 32 + 8 * g;   // 32B-aligned slice
            asm volatile(
                "st.global.cs.v8.f32 [%0], {%1,%2,%3,%4,%5,%6,%7,%8};"
                :: "l"(dst),
                   "f"(f[0]), "f"(f[1]), "f"(f[2]), "f"(f[3]),
                   "f"(f[4]), "f"(f[5]), "f"(f[6]), "f"(f[7])
                : "memory");
        }
    } else {
        // ---------------- hash warps: 2 threads/point, 2 levels each ----------------
        const int h    = (wid - 3) * 32 + lane;  // 0..63
        const int pt   = h >> 1;                 // 0..31
        const int half = h & 1;
        const int p  = pbase + pt;
        const bool valid = (p < npts);
        const int  pl = valid ? p : (npts - 1);
        const int jbase = 2 * half;              // level offset within 12..15

        const float2 xv = __ldg((const float2*)x + pl);
        const float x0 = xv.x, x1 = xv.y;

        float w0s[2], w1s[2], f[4];
        int idxs[8];
#pragma unroll
        for (int j = 0; j < 2; j++) {
            const int lj  = jbase + j;                 // 0..3
            const int lvl = NDENSE + lj;
            int li  = (lj < L) ? lj : (L - 1);
            int len = __ldg(lengths + li);             // (res+1)^2, exact in f32
            int res = (int)__fsqrt_rn((float)len) - 1; // exact integer sqrt
            float gs = __fdiv_rn(2048.0f, (float)res); // == f64-then-f32 (proven)

            float q0  = div_full(x0, gs);
            float q1  = div_full(x1, gs);
            float b0f = floorf(q0), b1f = floorf(q1);
            int   b0  = (int)b0f,   b1  = (int)b1f;
            float mn0 = b0f * gs,   mn1 = b1f * gs;
            w0s[j] = __fdividef(x0 - mn0, (mn0 + gs) - mn0);
            w1s[j] = __fdividef(x1 - mn1, (mn1 + gs) - mn1);

            unsigned g0 = (unsigned)b0, g1 = (unsigned)b1;
            unsigned h00 = (g0        ^ (g1        * HPRIME)) & HMASK;
            unsigned h01 = (g0        ^ ((g1 + 1u) * HPRIME)) & HMASK;
            unsigned h10 = ((g0 + 1u) ^ (g1        * HPRIME)) & HMASK;
            unsigned h11 = ((g0 + 1u) ^ ((g1 + 1u) * HPRIME)) & HMASK;

            if ((unsigned)b0 < (unsigned)res && (unsigned)b1 < (unsigned)res) {
                // All 4 corners present in table => searchsorted returns the hash.
                idxs[4 * j + 0] = (int)h00; idxs[4 * j + 1] = (int)h01;
                idxs[4 * j + 2] = (int)h10; idxs[4 * j + 3] = (int)h11;
            } else {
                long long ro = (long long)li * maxP;
                idxs[4 * j + 0] = cons_lookup(tk, tv, ro, len, h00);
                idxs[4 * j + 1] = cons_lookup(tk, tv, ro, len, h01);
                idxs[4 * j + 2] = cons_lookup(tk, tv, ro, len, h10);
                idxs[4 * j + 3] = cons_lookup(tk, tv, ro, len, h11);
            }

            if (valid) {
                float4 v = make_float4((float)idxs[4 * j + 0], (float)idxs[4 * j + 1],
                                       (float)idxs[4 * j + 2], (float)idxs[4 * j + 3]);
                __stcs((float4*)(out + idxbase + ((size_t)lvl * npts + p) * 4), v);
            }
        }

#pragma unroll
        for (int j = 0; j < 2; j++) {
            const int lvl = NDENSE + jbase + j;
            const float2* tb = (const float2*)tables + (size_t)lvl * TSIZE;
            float2 e00 = __ldg(tb + idxs[4 * j + 0]);
            float2 e01 = __ldg(tb + idxs[4 * j + 1]);
            float2 e10 = __ldg(tb + idxs[4 * j + 2]);
            float2 e11 = __ldg(tb + idxs[4 * j + 3]);

            float w0 = w0s[j], w1 = w1s[j];
            float om0 = 1.0f - w0, om1 = 1.0f - w1;
            float c0x = e00.x * om1 + e01.x * w1;
            float c1x = e10.x * om1 + e11.x * w1;
            float c0y = e00.y * om1 + e01.y * w1;
            float c1y = e10.y * om1 + e11.y * w1;
            f[2 * j]     = c0x * om0 + c1x * w0;
            f[2 * j + 1] = c0y * om0 + c1y * w0;
        }

        if (valid) {
            // 16B slice: levels {12,13} at +96 (half=0) or {14,15} at +112.
            __stcs((float4*)(out + (size_t)p * 32 + 24 + 4 * half),
                   make_float4(f[0], f[1], f[2], f[3]));
        }
    }
}

extern "C" void kernel_launch(void* const* d_in, const int* in_sizes, int n_in,
                              void* d_out, int out_size)
{
    const float* x       = (const float*)d_in[0];
    const float* tables  = (const float*)d_in[1];
    const int*   tk      = (const int*)d_in[2];
    const int*   tv      = (const int*)d_in[3];
    const int*   lengths = (const int*)d_in[4];

    int L    = in_sizes[4];
    int maxP = in_sizes[2] / (L > 0 ? L : 1);
    int npts = in_sizes[0] / 2;

    fill_quad_kernel<<<(QTOTAL + BLK - 1) / BLK, BLK>>>(tables);

    int blocks = (npts + PTS_PER_BLK - 1) / PTS_PER_BLK;
    hashgrid_kernel<<<blocks, BLKT>>>(x, tables, tk, tv, lengths, L, maxP,
                                      (float*)d_out, npts);
}

// round 16
// speedup vs baseline: 1.1767x; 1.0736x over previous
#include <cuda_runtime.h>
#include <math.h>

#define NLEV   16
#define NDENSE 12
#define NCONS  4
#define TSIZE  524288
#define HPRIME 2654435761u
#define HMASK  524287u
#define BLK    256          // fill kernel block
#define BLKT   192          // main kernel: 6 warps
#define DPTS   64           // points per dense block (192 thr / 3)
#define HPTS   96           // points per hash block  (192 thr / 2)

// Dense-level resolutions (float32 np.power chain margins all >> ulp error).
__device__ __constant__ int   RESD[NDENSE] = {16,22,30,42,58,80,111,153,212,294,406,561};
__device__ __constant__ float GSD[NDENSE] = {
    (float)(2048.0/16.0),  (float)(2048.0/22.0),  (float)(2048.0/30.0),
    (float)(2048.0/42.0),  (float)(2048.0/58.0),  (float)(2048.0/80.0),
    (float)(2048.0/111.0), (float)(2048.0/153.0), (float)(2048.0/212.0),
    (float)(2048.0/294.0), (float)(2048.0/406.0), (float)(2048.0/561.0)
};

// Quad table: g_quad[(QOFF[l]+c)*8 ..] = table_l[c], table_l[c+1],
// table_l[c+res], table_l[c+res+1] (8 floats = 32B per cell).
// One 32B v8 load fetches ALL FOUR corners of a dense cell.
#define QTOTAL 661844
__device__ __align__(32) float g_quad[QTOTAL * 8];
__constant__ int QOFF[13] = {0,274,782,1714,3522,6946,13428,25862,49426,
                             94584,181316,346560,661844};

// Build the quad table (runs inside the captured graph; coalesced, few us).
__global__ void fill_quad_kernel(const float* __restrict__ tables)
{
    int idx = blockIdx.x * BLK + threadIdx.x;
    if (idx >= QTOTAL) return;
    int l = 0;
#pragma unroll
    for (int i = 1; i < NDENSE; i++) if (idx >= QOFF[i]) l = i;
    int c   = idx - QOFF[l];
    int res = RESD[l];
    const float2* tb2 = (const float2*)tables + (size_t)l * TSIZE;
    float2 e0 = __ldg(tb2 + c);
    float2 e1 = __ldg(tb2 + c + 1);
    float2 e2 = __ldg(tb2 + c + res);
    float2 e3 = __ldg(tb2 + c + res + 1);
    float* q = g_quad + (size_t)idx * 8;
    *(float4*)q       = make_float4(e0.x, e0.y, e1.x, e1.y);
    *(float4*)(q + 4) = make_float4(e2.x, e2.y, e3.x, e3.y);
}

// XLA:GPU emits approximate full-range division (div.full.f32) for f32 divide.
// Required for bit-exact bl = floor(x/gs) at cell boundaries.
__device__ __forceinline__ float div_full(float a, float b)
{
    float r;
    asm("div.full.f32 %0, %1, %2;" : "=f"(r) : "f"(a), "f"(b));
    return r;
}

// Exact replica of jnp.searchsorted(tk_row, 2h) -> where(k==n,0,k) -> tv[k].
__device__ __forceinline__ int cons_lookup(const int* __restrict__ tk,
                                           const int* __restrict__ tv,
                                           long long rowoff, int n, unsigned h)
{
    int q  = 2 * (int)h;
    int lo = 0, hi = n;
    while (lo < hi) {
        int mid = (lo + hi) >> 1;
        if (__ldg(tk + rowoff + mid) < q) lo = mid + 1; else hi = mid;
    }
    if (lo == n) lo = 0;
    return __ldg(tv + rowoff + lo);
}

// HOMOGENEOUS BLOCKS (role by blockIdx — mixed blocks retire at the pace of
// their slowest warp; splitting roles at block granularity lets dense blocks
// free their SM resources immediately and lets the work distributor interleave
// long-latency hash blocks with short dense blocks continuously):
//   blocks [0, Nd):       dense, 192 thr = 64 pts (3 thr/pt, g=d%3 ->
//                         levels {4g..4g+3}); 4 x 32B v8 quad loads/thread.
//   blocks [Nd, Nd+Nh):   hash, 192 thr = 96 pts (2 thr/pt, half=h&1 ->
//                         levels {12+2*half, 13+2*half}); 8 random loads/thread.
// CONS params inline from lengths (exact recovery: len<2^24 exact in f32,
// sqrt of perfect square exact, single==double rounding for 2048/res).
// div.full for bl (bit-exact); __fdividef for w (feats-only, ~2ulp).
__global__ __launch_bounds__(BLKT, 8)
void hashgrid_kernel(const float* __restrict__ x,
                     const float* __restrict__ tables,
                     const int*   __restrict__ tk,
                     const int*   __restrict__ tv,
                     const int*   __restrict__ lengths,
                     int L, int maxP, int Nd,
                     float* __restrict__ out,
                     int npts)
{
    const int tid = threadIdx.x;
    const size_t idxbase = (size_t)npts * 32;

    if ((int)blockIdx.x < Nd) {
        // ---------------- dense block ----------------
        const int pt = tid / 3;               // 0..63
        const int g  = tid - 3 * pt;          // 0..2
        const int p  = blockIdx.x * DPTS + pt;
        const bool valid = (p < npts);
        const int  pl = valid ? p : (npts - 1);
        const int lvl0 = 4 * g;

        const float2 xv = __ldg((const float2*)x + pl);
        const float x0 = xv.x, x1 = xv.y;

        float w0s[4], w1s[4], f[8];
        int cells[4];
#pragma unroll
        for (int j = 0; j < 4; j++) {
            const int lvl = lvl0 + j;
            const int   res = RESD[lvl];
            const float gs  = GSD[lvl];

            float q0  = div_full(x0, gs);
            float q1  = div_full(x1, gs);
            float b0f = floorf(q0), b1f = floorf(q1);
            int   b0  = (int)b0f,   b1  = (int)b1f;
            float mn0 = b0f * gs,   mn1 = b1f * gs;
            w0s[j] = __fdividef(x0 - mn0, (mn0 + gs) - mn0);
            w1s[j] = __fdividef(x1 - mn1, (mn1 + gs) - mn1);

            int i00 = b0 * res + b1;
            cells[j] = i00;

            if (valid) {
                float4 v = make_float4((float)i00, (float)(i00 + 1),
                                       (float)(i00 + res), (float)(i00 + res + 1));
                __stcs((float4*)(out + idxbase + ((size_t)lvl * npts + p) * 4), v);
            }
        }

#pragma unroll
        for (int j = 0; j < 4; j++) {
            const int lvl = lvl0 + j;
            const float* qp = g_quad + (size_t)(QOFF[lvl] + cells[j]) * 8;
            float r0, r1, r2, r3, r4, r5, r6, r7;
            asm("ld.global.v8.f32 {%0,%1,%2,%3,%4,%5,%6,%7}, [%8];"
                : "=f"(r0), "=f"(r1), "=f"(r2), "=f"(r3),
                  "=f"(r4), "=f"(r5), "=f"(r6), "=f"(r7)
                : "l"(qp));

            float w0 = w0s[j], w1 = w1s[j];
            float om0 = 1.0f - w0, om1 = 1.0f - w1;
            float c0x = r0 * om1 + r2 * w1;
            float c0y = r1 * om1 + r3 * w1;
            float c1x = r4 * om1 + r6 * w1;
            float c1y = r5 * om1 + r7 * w1;
            f[2 * j]     = c0x * om0 + c1x * w0;
            f[2 * j + 1] = c0y * om0 + c1y * w0;
        }

        if (valid) {
            float* dst = out + (size_t)p * 32 + 8 * g;   // 32B-aligned slice
            asm volatile(
                "st.global.cs.v8.f32 [%0], {%1,%2,%3,%4,%5,%6,%7,%8};"
                :: "l"(dst),
                   "f"(f[0]), "f"(f[1]), "f"(f[2]), "f"(f[3]),
                   "f"(f[4]), "f"(f[5]), "f"(f[6]), "f"(f[7])
                : "memory");
        }
    } else {
        // ---------------- hash block: 2 threads/point, 2 levels each ----------------
        const int pt   = tid >> 1;               // 0..95
        const int half = tid & 1;
        const int p  = ((int)blockIdx.x - Nd) * HPTS + pt;
        const bool valid = (p < npts);
        const int  pl = valid ? p : (npts - 1);
        const int jbase = 2 * half;

        const float2 xv = __ldg((const float2*)x + pl);
        const float x0 = xv.x, x1 = xv.y;

        float w0s[2], w1s[2], f[4];
        int idxs[8];
#pragma unroll
        for (int j = 0; j < 2; j++) {
            const int lj  = jbase + j;                 // 0..3
            const int lvl = NDENSE + lj;
            int li  = (lj < L) ? lj : (L - 1);
            int len = __ldg(lengths + li);             // (res+1)^2, exact in f32
            int res = (int)__fsqrt_rn((float)len) - 1; // exact integer sqrt
            float gs = __fdiv_rn(2048.0f, (float)res); // == f64-then-f32 (proven)

            float q0  = div_full(x0, gs);
            float q1  = div_full(x1, gs);
            float b0f = floorf(q0), b1f = floorf(q1);
            int   b0  = (int)b0f,   b1  = (int)b1f;
            float mn0 = b0f * gs,   mn1 = b1f * gs;
            w0s[j] = __fdividef(x0 - mn0, (mn0 + gs) - mn0);
            w1s[j] = __fdividef(x1 - mn1, (mn1 + gs) - mn1);

            unsigned g0 = (unsigned)b0, g1 = (unsigned)b1;
            unsigned h00 = (g0        ^ (g1        * HPRIME)) & HMASK;
            unsigned h01 = (g0        ^ ((g1 + 1u) * HPRIME)) & HMASK;
            unsigned h10 = ((g0 + 1u) ^ (g1        * HPRIME)) & HMASK;
            unsigned h11 = ((g0 + 1u) ^ ((g1 + 1u) * HPRIME)) & HMASK;

            if ((unsigned)b0 < (unsigned)res && (unsigned)b1 < (unsigned)res) {
                // All 4 corners present in table => searchsorted returns the hash.
                idxs[4 * j + 0] = (int)h00; idxs[4 * j + 1] = (int)h01;
                idxs[4 * j + 2] = (int)h10; idxs[4 * j + 3] = (int)h11;
            } else {
                long long ro = (long long)li * maxP;
                idxs[4 * j + 0] = cons_lookup(tk, tv, ro, len, h00);
                idxs[4 * j + 1] = cons_lookup(tk, tv, ro, len, h01);
                idxs[4 * j + 2] = cons_lookup(tk, tv, ro, len, h10);
                idxs[4 * j + 3] = cons_lookup(tk, tv, ro, len, h11);
            }

            if (valid) {
                float4 v = make_float4((float)idxs[4 * j + 0], (float)idxs[4 * j + 1],
                                       (float)idxs[4 * j + 2], (float)idxs[4 * j + 3]);
                __stcs((float4*)(out + idxbase + ((size_t)lvl * npts + p) * 4), v);
            }
        }

#pragma unroll
        for (int j = 0; j < 2; j++) {
            const int lvl = NDENSE + jbase + j;
            const float2* tb = (const float2*)tables + (size_t)lvl * TSIZE;
            float2 e00 = __ldg(tb + idxs[4 * j + 0]);
            float2 e01 = __ldg(tb + idxs[4 * j + 1]);
            float2 e10 = __ldg(tb + idxs[4 * j + 2]);
            float2 e11 = __ldg(tb + idxs[4 * j + 3]);

            float w0 = w0s[j], w1 = w1s[j];
            float om0 = 1.0f - w0, om1 = 1.0f - w1;
            float c0x = e00.x * om1 + e01.x * w1;
            float c1x = e10.x * om1 + e11.x * w1;
            float c0y = e00.y * om1 + e01.y * w1;
            float c1y = e10.y * om1 + e11.y * w1;
            f[2 * j]     = c0x * om0 + c1x * w0;
            f[2 * j + 1] = c0y * om0 + c1y * w0;
        }

        if (valid) {
            // 16B slice: levels {12,13} at +96B (half=0) or {14,15} at +112B.
            __stcs((float4*)(out + (size_t)p * 32 + 24 + 4 * half),
                   make_float4(f[0], f[1], f[2], f[3]));
        }
    }
}

extern "C" void kernel_launch(void* const* d_in, const int* in_sizes, int n_in,
                              void* d_out, int out_size)
{
    const float* x       = (const float*)d_in[0];
    const float* tables  = (const float*)d_in[1];
    const int*   tk      = (const int*)d_in[2];
    const int*   tv      = (const int*)d_in[3];
    const int*   lengths = (const int*)d_in[4];

    int L    = in_sizes[4];
    int maxP = in_sizes[2] / (L > 0 ? L : 1);
    int npts = in_sizes[0] / 2;

    fill_quad_kernel<<<(QTOTAL + BLK - 1) / BLK, BLK>>>(tables);

    int Nd = (npts + DPTS - 1) / DPTS;
    int Nh = (npts + HPTS - 1) / HPTS;
    hashgrid_kernel<<<Nd + Nh, BLKT>>>(x, tables, tk, tv, lengths, L, maxP, Nd,
                                       (float*)d_out, npts);
}